// round 2
// baseline (speedup 1.0000x reference)
#include <cuda_runtime.h>

#define TOKENS   8192      // 8 * 1024
#define DIMV     1024
#define HEADS    16
#define HD       64
#define NSEQ     1024
#define NBATCH   8
#define ATT_SCALE 0.125f   // 64^-0.5

// Scratch (no allocation allowed): QKV activations + attention output
__device__ float g_qkv[(size_t)TOKENS * 3 * DIMV];   // 96 MB
__device__ float g_att[(size_t)TOKENS * DIMV];       // 32 MB

// ---------------------------------------------------------------------------
// SGEMM core: C[M,N] = A[M,K] @ B[K,N] (+ bias). Block tile 128x128, BK=16,
// 256 threads, 8x8 register microtile. float4 global + smem traffic.
// M,N,K all multiples of tile dims for this problem -> no bounds checks.
// ---------------------------------------------------------------------------
template<bool BIAS>
__device__ __forceinline__ void gemm_core(const float* __restrict__ A,
                                          const float* __restrict__ Bw,
                                          const float* __restrict__ bias,
                                          float* __restrict__ C,
                                          int M, int N, int K) {
    __shared__ float As[16][132];   // transposed A tile, padded (row = k)
    __shared__ float Bs[16][128];   // B tile (row = k)

    const int tid  = threadIdx.x;
    const int tx   = tid & 15;      // 16 col groups
    const int ty   = tid >> 4;      // 16 row groups
    const int row0 = blockIdx.y * 128;
    const int col0 = blockIdx.x * 128;

    const float* Ab = A + (size_t)row0 * K;
    const float* Bb = Bw + col0;

    // A loader: thread -> (row = tid/2, 8 consecutive k at (tid&1)*8)
    const int a_row = tid >> 1;
    const int a_c0  = (tid & 1) * 8;
    // B loader: thread -> (k-row = tid/16, 8 consecutive n at (tid&15)*8)
    const int b_row = tid >> 4;
    const int b_c0  = (tid & 15) * 8;

    float acc[8][8];
    #pragma unroll
    for (int i = 0; i < 8; i++)
        #pragma unroll
        for (int j = 0; j < 8; j++) acc[i][j] = 0.f;

    for (int k0 = 0; k0 < K; k0 += 16) {
        float4 a0 = *reinterpret_cast<const float4*>(Ab + (size_t)a_row * K + k0 + a_c0);
        float4 a1 = *reinterpret_cast<const float4*>(Ab + (size_t)a_row * K + k0 + a_c0 + 4);
        float4 b0 = *reinterpret_cast<const float4*>(Bb + (size_t)(k0 + b_row) * N + b_c0);
        float4 b1 = *reinterpret_cast<const float4*>(Bb + (size_t)(k0 + b_row) * N + b_c0 + 4);

        As[a_c0 + 0][a_row] = a0.x; As[a_c0 + 1][a_row] = a0.y;
        As[a_c0 + 2][a_row] = a0.z; As[a_c0 + 3][a_row] = a0.w;
        As[a_c0 + 4][a_row] = a1.x; As[a_c0 + 5][a_row] = a1.y;
        As[a_c0 + 6][a_row] = a1.z; As[a_c0 + 7][a_row] = a1.w;
        *reinterpret_cast<float4*>(&Bs[b_row][b_c0])     = b0;
        *reinterpret_cast<float4*>(&Bs[b_row][b_c0 + 4]) = b1;
        __syncthreads();

        #pragma unroll
        for (int kk = 0; kk < 16; kk++) {
            float a[8], b[8];
            float4 av0 = *reinterpret_cast<const float4*>(&As[kk][ty * 8]);
            float4 av1 = *reinterpret_cast<const float4*>(&As[kk][ty * 8 + 4]);
            float4 bv0 = *reinterpret_cast<const float4*>(&Bs[kk][tx * 8]);
            float4 bv1 = *reinterpret_cast<const float4*>(&Bs[kk][tx * 8 + 4]);
            a[0]=av0.x; a[1]=av0.y; a[2]=av0.z; a[3]=av0.w;
            a[4]=av1.x; a[5]=av1.y; a[6]=av1.z; a[7]=av1.w;
            b[0]=bv0.x; b[1]=bv0.y; b[2]=bv0.z; b[3]=bv0.w;
            b[4]=bv1.x; b[5]=bv1.y; b[6]=bv1.z; b[7]=bv1.w;
            #pragma unroll
            for (int i = 0; i < 8; i++)
                #pragma unroll
                for (int j = 0; j < 8; j++)
                    acc[i][j] = fmaf(a[i], b[j], acc[i][j]);
        }
        __syncthreads();
    }

    #pragma unroll
    for (int i = 0; i < 8; i++) {
        const int r = row0 + ty * 8 + i;
        #pragma unroll
        for (int j = 0; j < 8; j += 4) {
            const int c = col0 + tx * 8 + j;
            float4 v;
            v.x = acc[i][j + 0];
            v.y = acc[i][j + 1];
            v.z = acc[i][j + 2];
            v.w = acc[i][j + 3];
            if (BIAS) {
                v.x += bias[c + 0]; v.y += bias[c + 1];
                v.z += bias[c + 2]; v.w += bias[c + 3];
            }
            *reinterpret_cast<float4*>(C + (size_t)r * N + c) = v;
        }
    }
}

__global__ __launch_bounds__(256) void qkv_gemm_kernel(const float* __restrict__ x,
                                                       const float* __restrict__ w) {
    gemm_core<false>(x, w, nullptr, g_qkv, TOKENS, 3 * DIMV, DIMV);
}

__global__ __launch_bounds__(256) void proj_gemm_kernel(const float* __restrict__ w,
                                                        const float* __restrict__ bias,
                                                        float* __restrict__ out) {
    gemm_core<true>(g_att, w, bias, out, TOKENS, DIMV, DIMV);
}

// ---------------------------------------------------------------------------
// Attention: one thread per query row, online softmax, K/V tiles in smem.
// grid.x = b*h (128), grid.y = query tile (8 x 128 rows), block = 128 threads.
// qkv layout per token (row of 3072): [q(16x64) | k(16x64) | v(16x64)]
// ---------------------------------------------------------------------------
__global__ __launch_bounds__(128) void attn_kernel() {
    const int bh = blockIdx.x;
    const int b  = bh >> 4;
    const int h  = bh & 15;
    const int qrow = blockIdx.y * 128 + threadIdx.x;
    const int t    = b * NSEQ + qrow;

    const float* qptr = g_qkv + (size_t)t * (3 * DIMV) + h * HD;
    float q[HD];
    #pragma unroll
    for (int d = 0; d < HD; d += 4) {
        float4 v = *reinterpret_cast<const float4*>(qptr + d);
        q[d] = v.x; q[d + 1] = v.y; q[d + 2] = v.z; q[d + 3] = v.w;
    }

    float acc[HD];
    #pragma unroll
    for (int d = 0; d < HD; d++) acc[d] = 0.f;
    float m = -1e30f, l = 0.f;

    __shared__ float Ks[64][HD];
    __shared__ float Vs[64][HD];

    const size_t kbase = (size_t)b * NSEQ * (3 * DIMV) + DIMV + h * HD;
    const size_t vbase = kbase + DIMV;

    for (int kt = 0; kt < NSEQ; kt += 64) {
        __syncthreads();
        // load 64x64 K and V tiles: 1024 float4 total, 8 per thread
        for (int i = threadIdx.x; i < 64 * (HD / 4); i += 128) {
            const int r = i >> 4;
            const int c = (i & 15) * 4;
            const size_t off = (size_t)(kt + r) * (3 * DIMV);
            *reinterpret_cast<float4*>(&Ks[r][c]) =
                *reinterpret_cast<const float4*>(g_qkv + kbase + off + c);
            *reinterpret_cast<float4*>(&Vs[r][c]) =
                *reinterpret_cast<const float4*>(g_qkv + vbase + off + c);
        }
        __syncthreads();

        for (int j = 0; j < 64; j++) {
            float s = 0.f;
            #pragma unroll
            for (int d = 0; d < HD; d++) s = fmaf(q[d], Ks[j][d], s);
            s *= ATT_SCALE;
            const float mnew = fmaxf(m, s);
            const float corr = __expf(m - mnew);
            const float p    = __expf(s - mnew);
            l = l * corr + p;
            #pragma unroll
            for (int d = 0; d < HD; d++)
                acc[d] = fmaf(acc[d], corr, p * Vs[j][d]);
            m = mnew;
        }
    }

    const float inv = 1.f / l;
    float* optr = g_att + (size_t)t * DIMV + h * HD;
    #pragma unroll
    for (int d = 0; d < HD; d += 4) {
        float4 v;
        v.x = acc[d] * inv; v.y = acc[d + 1] * inv;
        v.z = acc[d + 2] * inv; v.w = acc[d + 3] * inv;
        *reinterpret_cast<float4*>(optr + d) = v;
    }
}

// ---------------------------------------------------------------------------
extern "C" void kernel_launch(void* const* d_in, const int* in_sizes, int n_in,
                              void* d_out, int out_size) {
    const float* x      = (const float*)d_in[0];
    const float* w_qkv  = (const float*)d_in[1];
    const float* w_proj = (const float*)d_in[2];
    const float* b_proj = (const float*)d_in[3];
    float* out = (float*)d_out;

    dim3 g1((3 * DIMV) / 128, TOKENS / 128);   // (24, 64)
    qkv_gemm_kernel<<<g1, 256>>>(x, w_qkv);

    dim3 g2(NBATCH * HEADS, NSEQ / 128);       // (128, 8)
    attn_kernel<<<g2, 128>>>();

    dim3 g3(DIMV / 128, TOKENS / 128);         // (8, 64)
    proj_gemm_kernel<<<g3, 256>>>(w_proj, b_proj, out);
}

// round 4
// speedup vs baseline: 2.5386x; 2.5386x over previous
#include <cuda_runtime.h>
#include <cuda_bf16.h>
#include <cstdint>

#define TOKENS   8192
#define DIMV     1024
#define HEADS    16
#define HD       64
#define NSEQ     1024
#define NBATCH   8
#define ATT_SCALE 0.125f
#define N_QKV    3072

// ---------------- scratch (__device__ globals; no allocation) ---------------
__device__ float g_qkv[(size_t)TOKENS * N_QKV];
__device__ float g_att[(size_t)TOKENS * DIMV];
__device__ __nv_bfloat16 g_wqkv_h[(size_t)N_QKV * DIMV];
__device__ __nv_bfloat16 g_wqkv_l[(size_t)N_QKV * DIMV];
__device__ __nv_bfloat16 g_wproj_h[(size_t)DIMV * DIMV];
__device__ __nv_bfloat16 g_wproj_l[(size_t)DIMV * DIMV];

// ---------------- helpers ----------------
__device__ __forceinline__ uint32_t smem_u32(const void* p) {
    uint32_t a;
    asm("{ .reg .u64 t; cvta.to.shared.u64 t, %1; cvt.u32.u64 %0, t; }" : "=r"(a) : "l"(p));
    return a;
}

__device__ __forceinline__ void ldm4(uint32_t* r, uint32_t addr) {
    asm volatile("ldmatrix.sync.aligned.m8n8.x4.shared.b16 {%0,%1,%2,%3}, [%4];"
                 : "=r"(r[0]), "=r"(r[1]), "=r"(r[2]), "=r"(r[3]) : "r"(addr));
}

__device__ __forceinline__ void mma_bf16(float* d, const uint32_t* a,
                                         uint32_t b0, uint32_t b1) {
    asm volatile(
        "mma.sync.aligned.m16n8k16.row.col.f32.bf16.bf16.f32 "
        "{%0,%1,%2,%3}, {%4,%5,%6,%7}, {%8,%9}, {%0,%1,%2,%3};"
        : "+f"(d[0]), "+f"(d[1]), "+f"(d[2]), "+f"(d[3])
        : "r"(a[0]), "r"(a[1]), "r"(a[2]), "r"(a[3]), "r"(b0), "r"(b1));
}

__device__ __forceinline__ void bf16_split(float v, __nv_bfloat16& h, __nv_bfloat16& l) {
    h = __float2bfloat16(v);
    l = __float2bfloat16(v - __bfloat162float(h));
}

// ---------------------------------------------------------------------------
// Weight transpose + bf16 hi/lo split: W[K,N] -> Th/Tl[N,K]
// ---------------------------------------------------------------------------
__global__ __launch_bounds__(256) void transpose_split_kernel(
    const float* __restrict__ W, __nv_bfloat16* __restrict__ Th,
    __nv_bfloat16* __restrict__ Tl, int K, int N) {
    __shared__ float t[32][33];
    const int tx = threadIdx.x, ty = threadIdx.y;       // block (32, 8)
    const int k0 = blockIdx.x * 32, n0 = blockIdx.y * 32;
    #pragma unroll
    for (int i = 0; i < 4; i++)
        t[ty + i * 8][tx] = W[(size_t)(k0 + ty + i * 8) * N + (n0 + tx)];
    __syncthreads();
    #pragma unroll
    for (int i = 0; i < 4; i++) {
        const float v = t[tx][ty + i * 8];
        __nv_bfloat16 h, l;
        bf16_split(v, h, l);
        const size_t o = (size_t)(n0 + ty + i * 8) * K + (k0 + tx);
        Th[o] = h;
        Tl[o] = l;
    }
}

// ---------------------------------------------------------------------------
// bf16x3 mma.sync GEMM: C[M,N] = A[M,K] @ Bt[N,K]^T (+ bias)
// CTA tile 128x128, BK=32, 256 threads (2x4 warps), warp tile 64x32.
// ---------------------------------------------------------------------------
#define SPAD 40   // smem row stride in bf16 (80 B -> conflict-free ldmatrix)

template<bool BIAS>
__global__ __launch_bounds__(256) void gemm_bf16x3_kernel(
    const float* __restrict__ A, const __nv_bfloat16* __restrict__ Bh,
    const __nv_bfloat16* __restrict__ Bl, const float* __restrict__ bias,
    float* __restrict__ C, int M, int N, int K) {
    __shared__ __nv_bfloat16 sAh[128][SPAD];
    __shared__ __nv_bfloat16 sAl[128][SPAD];
    __shared__ __nv_bfloat16 sBh[128][SPAD];
    __shared__ __nv_bfloat16 sBl[128][SPAD];

    const int tid  = threadIdx.x;
    const int wid  = tid >> 5;
    const int lane = tid & 31;
    const int warp_m = wid & 1;           // 2 -> 64 rows each
    const int warp_n = wid >> 1;          // 4 -> 32 cols each
    const int row0 = blockIdx.y * 128, col0 = blockIdx.x * 128;

    const int lrow = tid >> 1;            // 0..127 loader row
    const int lk0  = (tid & 1) * 16;      // loader k offset (16 elems)

    const uint32_t ah_base = smem_u32(&sAh[0][0]);
    const uint32_t al_base = smem_u32(&sAl[0][0]);
    const uint32_t bh_base = smem_u32(&sBh[0][0]);
    const uint32_t bl_base = smem_u32(&sBl[0][0]);

    const int lr = lane & 15, ls = lane >> 4;   // ldmatrix lane mapping

    float acc[4][4][4];
    #pragma unroll
    for (int i = 0; i < 4; i++)
        #pragma unroll
        for (int j = 0; j < 4; j++)
            #pragma unroll
            for (int r = 0; r < 4; r++) acc[i][j][r] = 0.f;

    for (int k0 = 0; k0 < K; k0 += 32) {
        // --- load A fp32 tile, split to bf16 hi/lo ---
        #pragma unroll
        for (int i = 0; i < 4; i++) {
            const int kc = lk0 + i * 4;
            float4 v = *reinterpret_cast<const float4*>(
                A + (size_t)(row0 + lrow) * K + k0 + kc);
            __nv_bfloat16 hx, lx, hy, ly, hz, lz, hw, lw;
            bf16_split(v.x, hx, lx); bf16_split(v.y, hy, ly);
            bf16_split(v.z, hz, lz); bf16_split(v.w, hw, lw);
            __nv_bfloat162* ph = reinterpret_cast<__nv_bfloat162*>(&sAh[lrow][kc]);
            __nv_bfloat162* pl = reinterpret_cast<__nv_bfloat162*>(&sAl[lrow][kc]);
            ph[0] = __nv_bfloat162(hx, hy); ph[1] = __nv_bfloat162(hz, hw);
            pl[0] = __nv_bfloat162(lx, ly); pl[1] = __nv_bfloat162(lz, lw);
        }
        // --- load pre-split B bf16 tiles (K-major [N,K]) ---
        {
            const size_t go = (size_t)(col0 + lrow) * K + k0 + lk0;
            uint4 h0 = *reinterpret_cast<const uint4*>(Bh + go);
            uint4 h1 = *reinterpret_cast<const uint4*>(Bh + go + 8);
            uint4 l0 = *reinterpret_cast<const uint4*>(Bl + go);
            uint4 l1 = *reinterpret_cast<const uint4*>(Bl + go + 8);
            *reinterpret_cast<uint4*>(&sBh[lrow][lk0])     = h0;
            *reinterpret_cast<uint4*>(&sBh[lrow][lk0 + 8]) = h1;
            *reinterpret_cast<uint4*>(&sBl[lrow][lk0])     = l0;
            *reinterpret_cast<uint4*>(&sBl[lrow][lk0 + 8]) = l1;
        }
        __syncthreads();

        #pragma unroll
        for (int k16 = 0; k16 < 32; k16 += 16) {
            uint32_t a_h[4][4], a_l[4][4], b_h[2][4], b_l[2][4];
            #pragma unroll
            for (int mi = 0; mi < 4; mi++) {
                const int r = warp_m * 64 + mi * 16 + lr;
                const uint32_t off = (uint32_t)(r * SPAD + k16 + ls * 8) * 2;
                ldm4(a_h[mi], ah_base + off);
                ldm4(a_l[mi], al_base + off);
            }
            #pragma unroll
            for (int p = 0; p < 2; p++) {
                const int r = warp_n * 32 + p * 16 + lr;
                const uint32_t off = (uint32_t)(r * SPAD + k16 + ls * 8) * 2;
                ldm4(b_h[p], bh_base + off);
                ldm4(b_l[p], bl_base + off);
            }
            #pragma unroll
            for (int mi = 0; mi < 4; mi++)
                #pragma unroll
                for (int nj = 0; nj < 4; nj++) {
                    const int p = nj >> 1, s = nj & 1;
                    mma_bf16(acc[mi][nj], a_h[mi], b_h[p][s],     b_h[p][2 + s]);
                    mma_bf16(acc[mi][nj], a_h[mi], b_l[p][s],     b_l[p][2 + s]);
                    mma_bf16(acc[mi][nj], a_l[mi], b_h[p][s],     b_h[p][2 + s]);
                }
        }
        __syncthreads();
    }

    // --- epilogue ---
    const int er = lane >> 2, ec = (lane & 3) * 2;
    #pragma unroll
    for (int mi = 0; mi < 4; mi++) {
        #pragma unroll
        for (int nj = 0; nj < 4; nj++) {
            const int r = row0 + warp_m * 64 + mi * 16 + er;
            const int c = col0 + warp_n * 32 + nj * 8 + ec;
            float2 v0 = make_float2(acc[mi][nj][0], acc[mi][nj][1]);
            float2 v1 = make_float2(acc[mi][nj][2], acc[mi][nj][3]);
            if (BIAS) {
                const float b0 = bias[c], b1 = bias[c + 1];
                v0.x += b0; v0.y += b1;
                v1.x += b0; v1.y += b1;
            }
            *reinterpret_cast<float2*>(C + (size_t)r * N + c)       = v0;
            *reinterpret_cast<float2*>(C + (size_t)(r + 8) * N + c) = v1;
        }
    }
}

// ---------------------------------------------------------------------------
// Attention: 1 thread per query row, group-8 online softmax.
// ---------------------------------------------------------------------------
__global__ __launch_bounds__(128) void attn_kernel() {
    const int bh = blockIdx.x;
    const int b  = bh >> 4;
    const int h  = bh & 15;
    const int qrow = blockIdx.y * 128 + threadIdx.x;
    const int t    = b * NSEQ + qrow;

    const float* qptr = g_qkv + (size_t)t * N_QKV + h * HD;
    float q[HD];
    #pragma unroll
    for (int d = 0; d < HD; d += 4) {
        float4 v = *reinterpret_cast<const float4*>(qptr + d);
        q[d] = v.x; q[d + 1] = v.y; q[d + 2] = v.z; q[d + 3] = v.w;
    }
    float acc[HD];
    #pragma unroll
    for (int d = 0; d < HD; d++) acc[d] = 0.f;
    float m = -1e30f, l = 0.f;

    __shared__ float Ks[64][HD];
    __shared__ float Vs[64][HD];

    const size_t kbase = (size_t)b * NSEQ * N_QKV + DIMV + h * HD;
    const size_t vbase = kbase + DIMV;

    for (int kt = 0; kt < NSEQ; kt += 64) {
        __syncthreads();
        for (int i = threadIdx.x; i < 64 * (HD / 4); i += 128) {
            const int r = i >> 4;
            const int c = (i & 15) * 4;
            const size_t off = (size_t)(kt + r) * N_QKV;
            *reinterpret_cast<float4*>(&Ks[r][c]) =
                *reinterpret_cast<const float4*>(g_qkv + kbase + off + c);
            *reinterpret_cast<float4*>(&Vs[r][c]) =
                *reinterpret_cast<const float4*>(g_qkv + vbase + off + c);
        }
        __syncthreads();

        for (int jj = 0; jj < 64; jj += 8) {
            float s[8];
            #pragma unroll
            for (int u = 0; u < 8; u++) {
                float acc_s = 0.f;
                #pragma unroll
                for (int d = 0; d < HD; d++) acc_s = fmaf(q[d], Ks[jj + u][d], acc_s);
                s[u] = acc_s * ATT_SCALE;
            }
            float gm = s[0];
            #pragma unroll
            for (int u = 1; u < 8; u++) gm = fmaxf(gm, s[u]);
            const float mnew = fmaxf(m, gm);
            const float corr = __expf(m - mnew);
            l *= corr;
            #pragma unroll
            for (int d = 0; d < HD; d++) acc[d] *= corr;
            #pragma unroll
            for (int u = 0; u < 8; u++) {
                const float p = __expf(s[u] - mnew);
                l += p;
                #pragma unroll
                for (int d = 0; d < HD; d++)
                    acc[d] = fmaf(p, Vs[jj + u][d], acc[d]);
            }
            m = mnew;
        }
    }

    const float inv = 1.f / l;
    float* optr = g_att + (size_t)t * DIMV + h * HD;
    #pragma unroll
    for (int d = 0; d < HD; d += 4) {
        float4 v;
        v.x = acc[d] * inv;     v.y = acc[d + 1] * inv;
        v.z = acc[d + 2] * inv; v.w = acc[d + 3] * inv;
        *reinterpret_cast<float4*>(optr + d) = v;
    }
}

// ---------------------------------------------------------------------------
extern "C" void kernel_launch(void* const* d_in, const int* in_sizes, int n_in,
                              void* d_out, int out_size) {
    const float* x      = (const float*)d_in[0];
    const float* w_qkv  = (const float*)d_in[1];
    const float* w_proj = (const float*)d_in[2];
    const float* b_proj = (const float*)d_in[3];
    float* out = (float*)d_out;

    __nv_bfloat16 *wq_h, *wq_l, *wp_h, *wp_l;
    float *qkv, *att;
    cudaGetSymbolAddress((void**)&wq_h, g_wqkv_h);
    cudaGetSymbolAddress((void**)&wq_l, g_wqkv_l);
    cudaGetSymbolAddress((void**)&wp_h, g_wproj_h);
    cudaGetSymbolAddress((void**)&wp_l, g_wproj_l);
    cudaGetSymbolAddress((void**)&qkv, g_qkv);
    cudaGetSymbolAddress((void**)&att, g_att);

    // transpose + bf16-split weights
    transpose_split_kernel<<<dim3(DIMV / 32, N_QKV / 32), dim3(32, 8)>>>(
        w_qkv, wq_h, wq_l, DIMV, N_QKV);
    transpose_split_kernel<<<dim3(DIMV / 32, DIMV / 32), dim3(32, 8)>>>(
        w_proj, wp_h, wp_l, DIMV, DIMV);

    // qkv = x @ w_qkv
    gemm_bf16x3_kernel<false><<<dim3(N_QKV / 128, TOKENS / 128), 256>>>(
        x, wq_h, wq_l, nullptr, qkv, TOKENS, N_QKV, DIMV);

    // attention
    attn_kernel<<<dim3(NBATCH * HEADS, NSEQ / 128), 128>>>();

    // out = att @ w_proj + b
    gemm_bf16x3_kernel<true><<<dim3(DIMV / 128, TOKENS / 128), 256>>>(
        att, wp_h, wp_l, b_proj, out, TOKENS, DIMV, DIMV);
}

// round 6
// speedup vs baseline: 4.6226x; 1.8209x over previous
#include <cuda_runtime.h>
#include <cuda_bf16.h>
#include <cstdint>

#define TOKENS   8192
#define DIMV     1024
#define HEADS    16
#define HD       64
#define NSEQ     1024
#define NBATCH   8
#define ATT_SCALE 0.125f
#define N_QKV    3072
#define NBH      (NBATCH * HEADS)

// ---------------- scratch (__device__ globals; no allocation) ---------------
__device__ float g_qkv[(size_t)TOKENS * N_QKV];
__device__ float g_att[(size_t)TOKENS * DIMV];
__device__ __nv_bfloat16 g_wqkv_h[(size_t)N_QKV * DIMV];
__device__ __nv_bfloat16 g_wqkv_l[(size_t)N_QKV * DIMV];
__device__ __nv_bfloat16 g_wproj_h[(size_t)DIMV * DIMV];
__device__ __nv_bfloat16 g_wproj_l[(size_t)DIMV * DIMV];
// head-major split QKV: [bh][n][64]
__device__ __align__(16) __nv_bfloat16 g_qh[(size_t)NBH * NSEQ * HD];
__device__ __align__(16) __nv_bfloat16 g_ql[(size_t)NBH * NSEQ * HD];
__device__ __align__(16) __nv_bfloat16 g_kh[(size_t)NBH * NSEQ * HD];
__device__ __align__(16) __nv_bfloat16 g_kl[(size_t)NBH * NSEQ * HD];
__device__ __align__(16) __nv_bfloat16 g_vh[(size_t)NBH * NSEQ * HD];
__device__ __align__(16) __nv_bfloat16 g_vl[(size_t)NBH * NSEQ * HD];

// ---------------- helpers ----------------
__device__ __forceinline__ uint32_t smem_u32(const void* p) {
    uint32_t a;
    asm("{ .reg .u64 t; cvta.to.shared.u64 t, %1; cvt.u32.u64 %0, t; }" : "=r"(a) : "l"(p));
    return a;
}
__device__ __forceinline__ void ldm4(uint32_t* r, uint32_t addr) {
    asm volatile("ldmatrix.sync.aligned.m8n8.x4.shared.b16 {%0,%1,%2,%3}, [%4];"
                 : "=r"(r[0]), "=r"(r[1]), "=r"(r[2]), "=r"(r[3]) : "r"(addr));
}
__device__ __forceinline__ void ldm4t(uint32_t* r, uint32_t addr) {
    asm volatile("ldmatrix.sync.aligned.m8n8.x4.trans.shared.b16 {%0,%1,%2,%3}, [%4];"
                 : "=r"(r[0]), "=r"(r[1]), "=r"(r[2]), "=r"(r[3]) : "r"(addr));
}
__device__ __forceinline__ void mma_bf16(float* d, const uint32_t* a,
                                         uint32_t b0, uint32_t b1) {
    asm volatile(
        "mma.sync.aligned.m16n8k16.row.col.f32.bf16.bf16.f32 "
        "{%0,%1,%2,%3}, {%4,%5,%6,%7}, {%8,%9}, {%0,%1,%2,%3};"
        : "+f"(d[0]), "+f"(d[1]), "+f"(d[2]), "+f"(d[3])
        : "r"(a[0]), "r"(a[1]), "r"(a[2]), "r"(a[3]), "r"(b0), "r"(b1));
}
__device__ __forceinline__ void bf16_split(float v, __nv_bfloat16& h, __nv_bfloat16& l) {
    h = __float2bfloat16(v);
    l = __float2bfloat16(v - __bfloat162float(h));
}
__device__ __forceinline__ void split_pack(float a, float b, uint32_t& h, uint32_t& l) {
    __nv_bfloat16 ha = __float2bfloat16(a), hb = __float2bfloat16(b);
    float ra = a - __bfloat162float(ha), rb = b - __bfloat162float(hb);
    __nv_bfloat162 H(ha, hb);
    __nv_bfloat162 L(__float2bfloat16(ra), __float2bfloat16(rb));
    h = *reinterpret_cast<uint32_t*>(&H);
    l = *reinterpret_cast<uint32_t*>(&L);
}
#define CP_ASYNC16(s, g) asm volatile("cp.async.cg.shared.global [%0], [%1], 16;" :: "r"(s), "l"(g))
#define CP_COMMIT()      asm volatile("cp.async.commit_group;" ::: "memory")
#define CP_WAIT1()       asm volatile("cp.async.wait_group 1;" ::: "memory")
#define CP_WAIT0()       asm volatile("cp.async.wait_group 0;" ::: "memory")

// ---------------------------------------------------------------------------
// Weight transpose + bf16 hi/lo split: W[K,N] -> Th/Tl[N,K]
// ---------------------------------------------------------------------------
__global__ __launch_bounds__(256) void transpose_split_kernel(
    const float* __restrict__ W, __nv_bfloat16* __restrict__ Th,
    __nv_bfloat16* __restrict__ Tl, int K, int N) {
    __shared__ float t[32][33];
    const int tx = threadIdx.x, ty = threadIdx.y;
    const int k0 = blockIdx.x * 32, n0 = blockIdx.y * 32;
    #pragma unroll
    for (int i = 0; i < 4; i++)
        t[ty + i * 8][tx] = W[(size_t)(k0 + ty + i * 8) * N + (n0 + tx)];
    __syncthreads();
    #pragma unroll
    for (int i = 0; i < 4; i++) {
        const float v = t[tx][ty + i * 8];
        __nv_bfloat16 h, l;
        bf16_split(v, h, l);
        const size_t o = (size_t)(n0 + ty + i * 8) * K + (k0 + tx);
        Th[o] = h;
        Tl[o] = l;
    }
}

// ---------------------------------------------------------------------------
// split g_qkv -> head-major bf16 hi/lo Q(scaled)/K/V
// grid (TOKENS, 3), block 256; thread handles 4 contiguous dims
// ---------------------------------------------------------------------------
__global__ __launch_bounds__(256) void split_qkv_kernel() {
    const int t = blockIdx.x, c = blockIdx.y;
    const int d4 = threadIdx.x * 4;
    float4 v = *reinterpret_cast<const float4*>(
        g_qkv + (size_t)t * N_QKV + c * DIMV + d4);
    if (c == 0) { v.x *= ATT_SCALE; v.y *= ATT_SCALE; v.z *= ATT_SCALE; v.w *= ATT_SCALE; }
    const int h = d4 >> 6, dd = d4 & 63;
    const int b = t >> 10, n = t & 1023;
    const size_t o = ((size_t)(b * HEADS + h) * NSEQ + n) * HD + dd;
    __nv_bfloat16* dh = (c == 0) ? g_qh : (c == 1) ? g_kh : g_vh;
    __nv_bfloat16* dl = (c == 0) ? g_ql : (c == 1) ? g_kl : g_vl;
    __nv_bfloat16 h0, l0, h1, l1, h2, l2, h3, l3;
    bf16_split(v.x, h0, l0); bf16_split(v.y, h1, l1);
    bf16_split(v.z, h2, l2); bf16_split(v.w, h3, l3);
    *reinterpret_cast<__nv_bfloat162*>(dh + o)     = __nv_bfloat162(h0, h1);
    *reinterpret_cast<__nv_bfloat162*>(dh + o + 2) = __nv_bfloat162(h2, h3);
    *reinterpret_cast<__nv_bfloat162*>(dl + o)     = __nv_bfloat162(l0, l1);
    *reinterpret_cast<__nv_bfloat162*>(dl + o + 2) = __nv_bfloat162(l2, l3);
}

// ---------------------------------------------------------------------------
// bf16x3 mma.sync GEMM: C[M,N] = A[M,K] @ Bt[N,K]^T (+ bias)
// ---------------------------------------------------------------------------
#define SPAD 40

template<bool BIAS>
__global__ __launch_bounds__(256) void gemm_bf16x3_kernel(
    const float* __restrict__ A, const __nv_bfloat16* __restrict__ Bh,
    const __nv_bfloat16* __restrict__ Bl, const float* __restrict__ bias,
    float* __restrict__ C, int M, int N, int K) {
    __shared__ __nv_bfloat16 sAh[128][SPAD];
    __shared__ __nv_bfloat16 sAl[128][SPAD];
    __shared__ __nv_bfloat16 sBh[128][SPAD];
    __shared__ __nv_bfloat16 sBl[128][SPAD];

    const int tid  = threadIdx.x;
    const int wid  = tid >> 5;
    const int lane = tid & 31;
    const int warp_m = wid & 1;
    const int warp_n = wid >> 1;
    const int row0 = blockIdx.y * 128, col0 = blockIdx.x * 128;
    const int lrow = tid >> 1;
    const int lk0  = (tid & 1) * 16;

    const uint32_t ah_base = smem_u32(&sAh[0][0]);
    const uint32_t al_base = smem_u32(&sAl[0][0]);
    const uint32_t bh_base = smem_u32(&sBh[0][0]);
    const uint32_t bl_base = smem_u32(&sBl[0][0]);
    const int lr = lane & 15, ls = lane >> 4;

    float acc[4][4][4];
    #pragma unroll
    for (int i = 0; i < 4; i++)
        #pragma unroll
        for (int j = 0; j < 4; j++)
            #pragma unroll
            for (int r = 0; r < 4; r++) acc[i][j][r] = 0.f;

    for (int k0 = 0; k0 < K; k0 += 32) {
        #pragma unroll
        for (int i = 0; i < 4; i++) {
            const int kc = lk0 + i * 4;
            float4 v = *reinterpret_cast<const float4*>(
                A + (size_t)(row0 + lrow) * K + k0 + kc);
            __nv_bfloat16 hx, lx, hy, ly, hz, lz, hw, lw;
            bf16_split(v.x, hx, lx); bf16_split(v.y, hy, ly);
            bf16_split(v.z, hz, lz); bf16_split(v.w, hw, lw);
            __nv_bfloat162* ph = reinterpret_cast<__nv_bfloat162*>(&sAh[lrow][kc]);
            __nv_bfloat162* pl = reinterpret_cast<__nv_bfloat162*>(&sAl[lrow][kc]);
            ph[0] = __nv_bfloat162(hx, hy); ph[1] = __nv_bfloat162(hz, hw);
            pl[0] = __nv_bfloat162(lx, ly); pl[1] = __nv_bfloat162(lz, lw);
        }
        {
            const size_t go = (size_t)(col0 + lrow) * K + k0 + lk0;
            uint4 h0 = *reinterpret_cast<const uint4*>(Bh + go);
            uint4 h1 = *reinterpret_cast<const uint4*>(Bh + go + 8);
            uint4 l0 = *reinterpret_cast<const uint4*>(Bl + go);
            uint4 l1 = *reinterpret_cast<const uint4*>(Bl + go + 8);
            *reinterpret_cast<uint4*>(&sBh[lrow][lk0])     = h0;
            *reinterpret_cast<uint4*>(&sBh[lrow][lk0 + 8]) = h1;
            *reinterpret_cast<uint4*>(&sBl[lrow][lk0])     = l0;
            *reinterpret_cast<uint4*>(&sBl[lrow][lk0 + 8]) = l1;
        }
        __syncthreads();

        #pragma unroll
        for (int k16 = 0; k16 < 32; k16 += 16) {
            uint32_t a_h[4][4], a_l[4][4], b_h[2][4], b_l[2][4];
            #pragma unroll
            for (int mi = 0; mi < 4; mi++) {
                const int r = warp_m * 64 + mi * 16 + lr;
                const uint32_t off = (uint32_t)(r * SPAD + k16 + ls * 8) * 2;
                ldm4(a_h[mi], ah_base + off);
                ldm4(a_l[mi], al_base + off);
            }
            #pragma unroll
            for (int p = 0; p < 2; p++) {
                const int r = warp_n * 32 + p * 16 + lr;
                const uint32_t off = (uint32_t)(r * SPAD + k16 + ls * 8) * 2;
                ldm4(b_h[p], bh_base + off);
                ldm4(b_l[p], bl_base + off);
            }
            #pragma unroll
            for (int mi = 0; mi < 4; mi++)
                #pragma unroll
                for (int nj = 0; nj < 4; nj++) {
                    const int p = nj >> 1, s = nj & 1;
                    mma_bf16(acc[mi][nj], a_h[mi], b_h[p][s], b_h[p][2 + s]);
                    mma_bf16(acc[mi][nj], a_h[mi], b_l[p][s], b_l[p][2 + s]);
                    mma_bf16(acc[mi][nj], a_l[mi], b_h[p][s], b_h[p][2 + s]);
                }
        }
        __syncthreads();
    }

    const int er = lane >> 2, ec = (lane & 3) * 2;
    #pragma unroll
    for (int mi = 0; mi < 4; mi++) {
        #pragma unroll
        for (int nj = 0; nj < 4; nj++) {
            const int r = row0 + warp_m * 64 + mi * 16 + er;
            const int c = col0 + warp_n * 32 + nj * 8 + ec;
            float2 v0 = make_float2(acc[mi][nj][0], acc[mi][nj][1]);
            float2 v1 = make_float2(acc[mi][nj][2], acc[mi][nj][3]);
            if (BIAS) {
                const float b0 = bias[c], b1 = bias[c + 1];
                v0.x += b0; v0.y += b1;
                v1.x += b0; v1.y += b1;
            }
            *reinterpret_cast<float2*>(C + (size_t)r * N + c)       = v0;
            *reinterpret_cast<float2*>(C + (size_t)(r + 8) * N + c) = v1;
        }
    }
}

// ---------------------------------------------------------------------------
// Flash attention, mma.sync bf16x3. CTA: 128 q-rows, 8 warps, 16 K-tiles of 64.
// smem: 2 KV stages @ 32KB (kh/kl/vh/vl 8KB each) + Q hi/lo 32KB = 96KB.
// 16B-chunk XOR swizzle: offset(row, chunk) = (row*8 + (chunk ^ (row&7)))*16
// ---------------------------------------------------------------------------
#define ATT_SMEM 98304

__global__ __launch_bounds__(256) void attn_mma_kernel() {
    extern __shared__ char smem[];
    const uint32_t sb = smem_u32(smem);
    const int tid = threadIdx.x, wid = tid >> 5, lane = tid & 31;
    const int bh = blockIdx.x;
    const int qt0 = blockIdx.y * 128;
    const size_t hb = (size_t)bh * NSEQ * HD;

    // ---- issue Q loads (2048 16B chunks) ----
    {
        const __nv_bfloat16* qsrc[2] = {g_qh, g_ql};
        #pragma unroll
        for (int i = 0; i < 8; i++) {
            const int cid = tid + i * 256;
            const int arr = cid >> 10, rem = cid & 1023, row = rem >> 3, c = rem & 7;
            const void* g = qsrc[arr] + hb + (size_t)(qt0 + row) * HD + c * 8;
            const uint32_t s = sb + 65536 + arr * 16384 + (row * 8 + (c ^ (row & 7))) * 16;
            CP_ASYNC16(s, g);
        }
        CP_COMMIT();
    }
    // ---- KV tile loader ----
    auto load_kv = [&](int kt, int stage) {
        const __nv_bfloat16* src[4] = {g_kh, g_kl, g_vh, g_vl};
        const int key0 = kt * 64;
        #pragma unroll
        for (int i = 0; i < 8; i++) {
            const int cid = tid + i * 256;
            const int arr = cid >> 9, rem = cid & 511, key = rem >> 3, c = rem & 7;
            const void* g = src[arr] + hb + (size_t)(key0 + key) * HD + c * 8;
            const uint32_t s = sb + stage * 32768 + arr * 8192 +
                               (key * 8 + (c ^ (key & 7))) * 16;
            CP_ASYNC16(s, g);
        }
        CP_COMMIT();
    };
    load_kv(0, 0);

    CP_WAIT1();           // Q done (KV0 still in flight)
    __syncthreads();

    // ---- Q fragments (persist) ----
    uint32_t qfh[4][4], qfl[4][4];
    {
        const int row = wid * 16 + (lane & 15);
        #pragma unroll
        for (int ks = 0; ks < 4; ks++) {
            const int c = ks * 2 + (lane >> 4);
            const uint32_t off = (row * 8 + (c ^ (row & 7))) * 16;
            ldm4(qfh[ks], sb + 65536 + off);
            ldm4(qfl[ks], sb + 65536 + 16384 + off);
        }
    }

    float o[8][4];
    #pragma unroll
    for (int i = 0; i < 8; i++)
        #pragma unroll
        for (int j = 0; j < 4; j++) o[i][j] = 0.f;
    float m0 = -1e30f, m1 = -1e30f, l0 = 0.f, l1 = 0.f;

    for (int kt = 0; kt < 16; kt++) {
        const int stg = kt & 1;
        if (kt + 1 < 16) { load_kv(kt + 1, stg ^ 1); CP_WAIT1(); }
        else             { CP_WAIT0(); }
        __syncthreads();

        // ---- S = Q K^T (bf16x3) ----
        float sc[8][4];
        #pragma unroll
        for (int i = 0; i < 8; i++)
            #pragma unroll
            for (int j = 0; j < 4; j++) sc[i][j] = 0.f;
        const uint32_t kbh = sb + stg * 32768, kbl = kbh + 8192;
        #pragma unroll
        for (int ks = 0; ks < 4; ks++) {
            #pragma unroll
            for (int g = 0; g < 4; g++) {
                const int key = g * 16 + (lane & 15);
                const int c   = ks * 2 + (lane >> 4);
                const uint32_t off = (key * 8 + (c ^ (key & 7))) * 16;
                uint32_t kh4[4], kl4[4];
                ldm4(kh4, kbh + off);
                ldm4(kl4, kbl + off);
                #pragma unroll
                for (int s2 = 0; s2 < 2; s2++) {
                    float* d = sc[2 * g + s2];
                    mma_bf16(d, qfh[ks], kh4[s2], kh4[2 + s2]);
                    mma_bf16(d, qfh[ks], kl4[s2], kl4[2 + s2]);
                    mma_bf16(d, qfl[ks], kh4[s2], kh4[2 + s2]);
                }
            }
        }

        // ---- online softmax ----
        float mx0 = sc[0][0], mx1 = sc[0][2];
        #pragma unroll
        for (int nt = 0; nt < 8; nt++) {
            mx0 = fmaxf(mx0, fmaxf(sc[nt][0], sc[nt][1]));
            mx1 = fmaxf(mx1, fmaxf(sc[nt][2], sc[nt][3]));
        }
        mx0 = fmaxf(mx0, __shfl_xor_sync(0xffffffffu, mx0, 1));
        mx0 = fmaxf(mx0, __shfl_xor_sync(0xffffffffu, mx0, 2));
        mx1 = fmaxf(mx1, __shfl_xor_sync(0xffffffffu, mx1, 1));
        mx1 = fmaxf(mx1, __shfl_xor_sync(0xffffffffu, mx1, 2));
        const float mn0 = fmaxf(m0, mx0), mn1 = fmaxf(m1, mx1);
        const float c0 = __expf(m0 - mn0), c1 = __expf(m1 - mn1);
        float s0 = 0.f, s1 = 0.f;
        #pragma unroll
        for (int nt = 0; nt < 8; nt++) {
            float p0 = __expf(sc[nt][0] - mn0); sc[nt][0] = p0; s0 += p0;
            float p1 = __expf(sc[nt][1] - mn0); sc[nt][1] = p1; s0 += p1;
            float p2 = __expf(sc[nt][2] - mn1); sc[nt][2] = p2; s1 += p2;
            float p3 = __expf(sc[nt][3] - mn1); sc[nt][3] = p3; s1 += p3;
        }
        s0 += __shfl_xor_sync(0xffffffffu, s0, 1);
        s0 += __shfl_xor_sync(0xffffffffu, s0, 2);
        s1 += __shfl_xor_sync(0xffffffffu, s1, 1);
        s1 += __shfl_xor_sync(0xffffffffu, s1, 2);
        l0 = l0 * c0 + s0; l1 = l1 * c1 + s1;
        m0 = mn0; m1 = mn1;
        #pragma unroll
        for (int dt = 0; dt < 8; dt++) {
            o[dt][0] *= c0; o[dt][1] *= c0;
            o[dt][2] *= c1; o[dt][3] *= c1;
        }

        // ---- O += P V (bf16x3) ----
        const uint32_t vbh = sb + stg * 32768 + 16384, vbl = vbh + 8192;
        #pragma unroll
        for (int kk = 0; kk < 4; kk++) {
            uint32_t pah[4], pal[4];
            split_pack(sc[2 * kk][0],     sc[2 * kk][1],     pah[0], pal[0]);
            split_pack(sc[2 * kk][2],     sc[2 * kk][3],     pah[1], pal[1]);
            split_pack(sc[2 * kk + 1][0], sc[2 * kk + 1][1], pah[2], pal[2]);
            split_pack(sc[2 * kk + 1][2], sc[2 * kk + 1][3], pah[3], pal[3]);
            #pragma unroll
            for (int dg = 0; dg < 4; dg++) {
                const int key = kk * 16 + (lane & 15);
                const int c   = dg * 2 + (lane >> 4);
                const uint32_t off = (key * 8 + (c ^ (key & 7))) * 16;
                uint32_t vh4[4], vl4[4];
                ldm4t(vh4, vbh + off);
                ldm4t(vl4, vbl + off);
                mma_bf16(o[2 * dg], pah, vh4[0], vh4[1]);
                mma_bf16(o[2 * dg], pah, vl4[0], vl4[1]);
                mma_bf16(o[2 * dg], pal, vh4[0], vh4[1]);
                mma_bf16(o[2 * dg + 1], pah, vh4[2], vh4[3]);
                mma_bf16(o[2 * dg + 1], pah, vl4[2], vl4[3]);
                mma_bf16(o[2 * dg + 1], pal, vh4[2], vh4[3]);
            }
        }
        __syncthreads();
    }

    // ---- epilogue ----
    const float i0 = 1.f / l0, i1 = 1.f / l1;
    const int b = bh >> 4, h = bh & 15;
    const int r0 = qt0 + wid * 16 + (lane >> 2);
    float* base = g_att + (size_t)(b * NSEQ + r0) * DIMV + h * HD + (lane & 3) * 2;
    #pragma unroll
    for (int dt = 0; dt < 8; dt++) {
        float2 v0 = make_float2(o[dt][0] * i0, o[dt][1] * i0);
        float2 v1 = make_float2(o[dt][2] * i1, o[dt][3] * i1);
        *reinterpret_cast<float2*>(base + dt * 8)            = v0;
        *reinterpret_cast<float2*>(base + 8 * DIMV + dt * 8) = v1;
    }
}

// ---------------------------------------------------------------------------
extern "C" void kernel_launch(void* const* d_in, const int* in_sizes, int n_in,
                              void* d_out, int out_size) {
    const float* x      = (const float*)d_in[0];
    const float* w_qkv  = (const float*)d_in[1];
    const float* w_proj = (const float*)d_in[2];
    const float* b_proj = (const float*)d_in[3];
    float* out = (float*)d_out;

    __nv_bfloat16 *wq_h, *wq_l, *wp_h, *wp_l;
    float *qkv, *att;
    cudaGetSymbolAddress((void**)&wq_h, g_wqkv_h);
    cudaGetSymbolAddress((void**)&wq_l, g_wqkv_l);
    cudaGetSymbolAddress((void**)&wp_h, g_wproj_h);
    cudaGetSymbolAddress((void**)&wp_l, g_wproj_l);
    cudaGetSymbolAddress((void**)&qkv, g_qkv);
    cudaGetSymbolAddress((void**)&att, g_att);

    cudaFuncSetAttribute(attn_mma_kernel,
                         cudaFuncAttributeMaxDynamicSharedMemorySize, ATT_SMEM);

    transpose_split_kernel<<<dim3(DIMV / 32, N_QKV / 32), dim3(32, 8)>>>(
        w_qkv, wq_h, wq_l, DIMV, N_QKV);
    transpose_split_kernel<<<dim3(DIMV / 32, DIMV / 32), dim3(32, 8)>>>(
        w_proj, wp_h, wp_l, DIMV, DIMV);

    gemm_bf16x3_kernel<false><<<dim3(N_QKV / 128, TOKENS / 128), 256>>>(
        x, wq_h, wq_l, nullptr, qkv, TOKENS, N_QKV, DIMV);

    split_qkv_kernel<<<dim3(TOKENS, 3), 256>>>();

    attn_mma_kernel<<<dim3(NBH, NSEQ / 128), 256, ATT_SMEM>>>();

    gemm_bf16x3_kernel<true><<<dim3(DIMV / 128, TOKENS / 128), 256>>>(
        att, wp_h, wp_l, b_proj, out, TOKENS, DIMV, DIMV);
}

// round 8
// speedup vs baseline: 4.6539x; 1.0068x over previous
#include <cuda_runtime.h>
#include <cuda_bf16.h>
#include <cstdint>

#define TOKENS   8192
#define DIMV     1024
#define HEADS    16
#define HD       64
#define NSEQ     1024
#define NBATCH   8
#define ATT_SCALE 0.125f
#define N_QKV    3072
#define NBH      (NBATCH * HEADS)

// ---------------- scratch (__device__ globals; no allocation) ---------------
__device__ __align__(16) __nv_bfloat16 g_xh[(size_t)TOKENS * DIMV];
__device__ __align__(16) __nv_bfloat16 g_xl[(size_t)TOKENS * DIMV];
__device__ __align__(16) __nv_bfloat16 g_atth[(size_t)TOKENS * DIMV];
__device__ __align__(16) __nv_bfloat16 g_attl[(size_t)TOKENS * DIMV];
__device__ __align__(16) __nv_bfloat16 g_wqkv_h[(size_t)N_QKV * DIMV];
__device__ __align__(16) __nv_bfloat16 g_wqkv_l[(size_t)N_QKV * DIMV];
__device__ __align__(16) __nv_bfloat16 g_wproj_h[(size_t)DIMV * DIMV];
__device__ __align__(16) __nv_bfloat16 g_wproj_l[(size_t)DIMV * DIMV];
// head-major split QKV: [bh][n][64]
__device__ __align__(16) __nv_bfloat16 g_qh[(size_t)NBH * NSEQ * HD];
__device__ __align__(16) __nv_bfloat16 g_ql[(size_t)NBH * NSEQ * HD];
__device__ __align__(16) __nv_bfloat16 g_kh[(size_t)NBH * NSEQ * HD];
__device__ __align__(16) __nv_bfloat16 g_kl[(size_t)NBH * NSEQ * HD];
__device__ __align__(16) __nv_bfloat16 g_vh[(size_t)NBH * NSEQ * HD];
__device__ __align__(16) __nv_bfloat16 g_vl[(size_t)NBH * NSEQ * HD];

// ---------------- helpers ----------------
__device__ __forceinline__ uint32_t smem_u32(const void* p) {
    uint32_t a;
    asm("{ .reg .u64 t; cvta.to.shared.u64 t, %1; cvt.u32.u64 %0, t; }" : "=r"(a) : "l"(p));
    return a;
}
__device__ __forceinline__ void ldm4(uint32_t* r, uint32_t addr) {
    asm volatile("ldmatrix.sync.aligned.m8n8.x4.shared.b16 {%0,%1,%2,%3}, [%4];"
                 : "=r"(r[0]), "=r"(r[1]), "=r"(r[2]), "=r"(r[3]) : "r"(addr));
}
__device__ __forceinline__ void ldm4t(uint32_t* r, uint32_t addr) {
    asm volatile("ldmatrix.sync.aligned.m8n8.x4.trans.shared.b16 {%0,%1,%2,%3}, [%4];"
                 : "=r"(r[0]), "=r"(r[1]), "=r"(r[2]), "=r"(r[3]) : "r"(addr));
}
__device__ __forceinline__ void mma_bf16(float* d, const uint32_t* a,
                                         uint32_t b0, uint32_t b1) {
    asm volatile(
        "mma.sync.aligned.m16n8k16.row.col.f32.bf16.bf16.f32 "
        "{%0,%1,%2,%3}, {%4,%5,%6,%7}, {%8,%9}, {%0,%1,%2,%3};"
        : "+f"(d[0]), "+f"(d[1]), "+f"(d[2]), "+f"(d[3])
        : "r"(a[0]), "r"(a[1]), "r"(a[2]), "r"(a[3]), "r"(b0), "r"(b1));
}
__device__ __forceinline__ void bf16_split(float v, __nv_bfloat16& h, __nv_bfloat16& l) {
    h = __float2bfloat16(v);
    l = __float2bfloat16(v - __bfloat162float(h));
}
__device__ __forceinline__ void split_pack(float a, float b, uint32_t& h, uint32_t& l) {
    __nv_bfloat16 ha = __float2bfloat16(a), hb = __float2bfloat16(b);
    float ra = a - __bfloat162float(ha), rb = b - __bfloat162float(hb);
    __nv_bfloat162 H(ha, hb);
    __nv_bfloat162 L(__float2bfloat16(ra), __float2bfloat16(rb));
    h = *reinterpret_cast<uint32_t*>(&H);
    l = *reinterpret_cast<uint32_t*>(&L);
}
#define CP_ASYNC16(s, g) asm volatile("cp.async.cg.shared.global [%0], [%1], 16;" :: "r"(s), "l"(g))
#define CP_COMMIT()      asm volatile("cp.async.commit_group;" ::: "memory")
#define CP_WAIT1()       asm volatile("cp.async.wait_group 1;" ::: "memory")
#define CP_WAIT0()       asm volatile("cp.async.wait_group 0;" ::: "memory")

// ---------------------------------------------------------------------------
// Weight transpose + bf16 hi/lo split: W[K,N] -> Th/Tl[N,K]
// ---------------------------------------------------------------------------
__global__ __launch_bounds__(256) void transpose_split_kernel(
    const float* __restrict__ W, __nv_bfloat16* __restrict__ Th,
    __nv_bfloat16* __restrict__ Tl, int K, int N) {
    __shared__ float t[32][33];
    const int tx = threadIdx.x, ty = threadIdx.y;
    const int k0 = blockIdx.x * 32, n0 = blockIdx.y * 32;
    #pragma unroll
    for (int i = 0; i < 4; i++)
        t[ty + i * 8][tx] = W[(size_t)(k0 + ty + i * 8) * N + (n0 + tx)];
    __syncthreads();
    #pragma unroll
    for (int i = 0; i < 4; i++) {
        const float v = t[tx][ty + i * 8];
        __nv_bfloat16 h, l;
        bf16_split(v, h, l);
        const size_t o = (size_t)(n0 + ty + i * 8) * K + (k0 + tx);
        Th[o] = h;
        Tl[o] = l;
    }
}

// ---------------------------------------------------------------------------
// split x fp32 -> xh/xl bf16 (same layout)
// ---------------------------------------------------------------------------
__global__ __launch_bounds__(256) void split_x_kernel(const float* __restrict__ x) {
    const size_t o = (size_t)blockIdx.x * DIMV + threadIdx.x * 4;
    float4 v = *reinterpret_cast<const float4*>(x + o);
    uint32_t h0, l0, h1, l1;
    split_pack(v.x, v.y, h0, l0);
    split_pack(v.z, v.w, h1, l1);
    *reinterpret_cast<uint32_t*>(g_xh + o)     = h0;
    *reinterpret_cast<uint32_t*>(g_xh + o + 2) = h1;
    *reinterpret_cast<uint32_t*>(g_xl + o)     = l0;
    *reinterpret_cast<uint32_t*>(g_xl + o + 2) = l1;
}

// ---------------------------------------------------------------------------
// Pipelined bf16x3 GEMM, pre-split A: C = A @ Bt^T.
// MODE 1: fp32 C + bias.  MODE 2: scatter to split head-major QKV.
// 128x128 tile, BK=32, 256 threads, cp.async double buffer.
// ---------------------------------------------------------------------------
#define SPAD 40
#define ARR_BYTES (128 * SPAD * 2)     // 10240
#define GS_STAGE  (4 * ARR_BYTES)      // 40960
#define GS_SMEM   (2 * GS_STAGE)       // 81920

template<int MODE>
__global__ __launch_bounds__(256) void gemm_ps_kernel(
    const __nv_bfloat16* __restrict__ Ah, const __nv_bfloat16* __restrict__ Al,
    const __nv_bfloat16* __restrict__ Bh, const __nv_bfloat16* __restrict__ Bl,
    const float* __restrict__ bias, float* __restrict__ C,
    int M, int N, int K) {
    extern __shared__ char smem[];
    const uint32_t sb = smem_u32(smem);
    const int tid  = threadIdx.x;
    const int wid  = tid >> 5;
    const int lane = tid & 31;
    const int warp_m = wid & 1;
    const int warp_n = wid >> 1;
    const int row0 = blockIdx.y * 128, col0 = blockIdx.x * 128;
    const int lr = lane & 15, ls = lane >> 4;

    const __nv_bfloat16* srcs[4] = {Ah, Al, Bh, Bl};
    auto load_tile = [&](int kc, int stage) {
        const int k0 = kc * 32;
        #pragma unroll
        for (int i = 0; i < 8; i++) {
            const int cid = tid + i * 256;
            const int arr = cid >> 9, rem = cid & 511, row = rem >> 2, c = rem & 3;
            const int grow = (arr < 2 ? row0 : col0) + row;
            const void* g = srcs[arr] + (size_t)grow * K + k0 + c * 8;
            const uint32_t s = sb + stage * GS_STAGE + arr * ARR_BYTES + row * 80 + c * 16;
            CP_ASYNC16(s, g);
        }
        CP_COMMIT();
    };

    float acc[4][4][4];
    #pragma unroll
    for (int i = 0; i < 4; i++)
        #pragma unroll
        for (int j = 0; j < 4; j++)
            #pragma unroll
            for (int r = 0; r < 4; r++) acc[i][j][r] = 0.f;

    const int nchunks = K / 32;
    load_tile(0, 0);

    for (int kc = 0; kc < nchunks; kc++) {
        const int stg = kc & 1;
        if (kc + 1 < nchunks) { load_tile(kc + 1, stg ^ 1); CP_WAIT1(); }
        else                  { CP_WAIT0(); }
        __syncthreads();

        const uint32_t base = sb + stg * GS_STAGE;
        #pragma unroll
        for (int k16 = 0; k16 < 32; k16 += 16) {
            uint32_t a_h[4][4], a_l[4][4], b_h[2][4], b_l[2][4];
            #pragma unroll
            for (int mi = 0; mi < 4; mi++) {
                const int r = warp_m * 64 + mi * 16 + lr;
                const uint32_t off = (uint32_t)(r * SPAD + k16 + ls * 8) * 2;
                ldm4(a_h[mi], base + off);
                ldm4(a_l[mi], base + ARR_BYTES + off);
            }
            #pragma unroll
            for (int p = 0; p < 2; p++) {
                const int r = warp_n * 32 + p * 16 + lr;
                const uint32_t off = (uint32_t)(r * SPAD + k16 + ls * 8) * 2;
                ldm4(b_h[p], base + 2 * ARR_BYTES + off);
                ldm4(b_l[p], base + 3 * ARR_BYTES + off);
            }
            #pragma unroll
            for (int mi = 0; mi < 4; mi++)
                #pragma unroll
                for (int nj = 0; nj < 4; nj++) {
                    const int p = nj >> 1, s = nj & 1;
                    mma_bf16(acc[mi][nj], a_h[mi], b_h[p][s], b_h[p][2 + s]);
                    mma_bf16(acc[mi][nj], a_h[mi], b_l[p][s], b_l[p][2 + s]);
                    mma_bf16(acc[mi][nj], a_l[mi], b_h[p][s], b_h[p][2 + s]);
                }
        }
        __syncthreads();
    }

    // ---- epilogue ----
    const int er = lane >> 2, ec = (lane & 3) * 2;
    if (MODE == 2) {
        auto scatter = [&](int r, int c, float x, float y) {
            const int qi = c >> 10, dcol = c & 1023;
            const int head = dcol >> 6, dd = dcol & 63;
            const int b = r >> 10, n = r & 1023;
            const size_t off = (((size_t)(b * HEADS + head) * NSEQ) + n) * HD + dd;
            if (qi == 0) { x *= ATT_SCALE; y *= ATT_SCALE; }
            uint32_t h, l;
            split_pack(x, y, h, l);
            __nv_bfloat16* dh = (qi == 0) ? g_qh : (qi == 1) ? g_kh : g_vh;
            __nv_bfloat16* dl = (qi == 0) ? g_ql : (qi == 1) ? g_kl : g_vl;
            *reinterpret_cast<uint32_t*>(dh + off) = h;
            *reinterpret_cast<uint32_t*>(dl + off) = l;
        };
        #pragma unroll
        for (int mi = 0; mi < 4; mi++)
            #pragma unroll
            for (int nj = 0; nj < 4; nj++) {
                const int r = row0 + warp_m * 64 + mi * 16 + er;
                const int c = col0 + warp_n * 32 + nj * 8 + ec;
                scatter(r,     c, acc[mi][nj][0], acc[mi][nj][1]);
                scatter(r + 8, c, acc[mi][nj][2], acc[mi][nj][3]);
            }
    } else {
        #pragma unroll
        for (int mi = 0; mi < 4; mi++)
            #pragma unroll
            for (int nj = 0; nj < 4; nj++) {
                const int r = row0 + warp_m * 64 + mi * 16 + er;
                const int c = col0 + warp_n * 32 + nj * 8 + ec;
                float2 v0 = make_float2(acc[mi][nj][0], acc[mi][nj][1]);
                float2 v1 = make_float2(acc[mi][nj][2], acc[mi][nj][3]);
                if (MODE == 1) {
                    const float b0 = bias[c], b1 = bias[c + 1];
                    v0.x += b0; v0.y += b1;
                    v1.x += b0; v1.y += b1;
                }
                *reinterpret_cast<float2*>(C + (size_t)r * N + c)       = v0;
                *reinterpret_cast<float2*>(C + (size_t)(r + 8) * N + c) = v1;
            }
    }
}

// ---------------------------------------------------------------------------
// Flash attention, mma.sync bf16x3 (R6-proven). Epilogue writes split bf16.
// ---------------------------------------------------------------------------
#define ATT_SMEM 98304

__global__ __launch_bounds__(256) void attn_mma_kernel() {
    extern __shared__ char smem[];
    const uint32_t sb = smem_u32(smem);
    const int tid = threadIdx.x, wid = tid >> 5, lane = tid & 31;
    const int bh = blockIdx.x;
    const int qt0 = blockIdx.y * 128;
    const size_t hb = (size_t)bh * NSEQ * HD;

    {
        const __nv_bfloat16* qsrc[2] = {g_qh, g_ql};
        #pragma unroll
        for (int i = 0; i < 8; i++) {
            const int cid = tid + i * 256;
            const int arr = cid >> 10, rem = cid & 1023, row = rem >> 3, c = rem & 7;
            const void* g = qsrc[arr] + hb + (size_t)(qt0 + row) * HD + c * 8;
            const uint32_t s = sb + 65536 + arr * 16384 + (row * 8 + (c ^ (row & 7))) * 16;
            CP_ASYNC16(s, g);
        }
        CP_COMMIT();
    }
    auto load_kv = [&](int kt, int stage) {
        const __nv_bfloat16* src[4] = {g_kh, g_kl, g_vh, g_vl};
        const int key0 = kt * 64;
        #pragma unroll
        for (int i = 0; i < 8; i++) {
            const int cid = tid + i * 256;
            const int arr = cid >> 9, rem = cid & 511, key = rem >> 3, c = rem & 7;
            const void* g = src[arr] + hb + (size_t)(key0 + key) * HD + c * 8;
            const uint32_t s = sb + stage * 32768 + arr * 8192 +
                               (key * 8 + (c ^ (key & 7))) * 16;
            CP_ASYNC16(s, g);
        }
        CP_COMMIT();
    };
    load_kv(0, 0);

    CP_WAIT1();
    __syncthreads();

    uint32_t qfh[4][4], qfl[4][4];
    {
        const int row = wid * 16 + (lane & 15);
        #pragma unroll
        for (int ks = 0; ks < 4; ks++) {
            const int c = ks * 2 + (lane >> 4);
            const uint32_t off = (row * 8 + (c ^ (row & 7))) * 16;
            ldm4(qfh[ks], sb + 65536 + off);
            ldm4(qfl[ks], sb + 65536 + 16384 + off);
        }
    }

    float o[8][4];
    #pragma unroll
    for (int i = 0; i < 8; i++)
        #pragma unroll
        for (int j = 0; j < 4; j++) o[i][j] = 0.f;
    float m0 = -1e30f, m1 = -1e30f, l0 = 0.f, l1 = 0.f;

    for (int kt = 0; kt < 16; kt++) {
        const int stg = kt & 1;
        if (kt + 1 < 16) { load_kv(kt + 1, stg ^ 1); CP_WAIT1(); }
        else             { CP_WAIT0(); }
        __syncthreads();

        float sc[8][4];
        #pragma unroll
        for (int i = 0; i < 8; i++)
            #pragma unroll
            for (int j = 0; j < 4; j++) sc[i][j] = 0.f;
        const uint32_t kbh = sb + stg * 32768, kbl = kbh + 8192;
        #pragma unroll
        for (int ks = 0; ks < 4; ks++) {
            #pragma unroll
            for (int g = 0; g < 4; g++) {
                const int key = g * 16 + (lane & 15);
                const int c   = ks * 2 + (lane >> 4);
                const uint32_t off = (key * 8 + (c ^ (key & 7))) * 16;
                uint32_t kh4[4], kl4[4];
                ldm4(kh4, kbh + off);
                ldm4(kl4, kbl + off);
                #pragma unroll
                for (int s2 = 0; s2 < 2; s2++) {
                    float* d = sc[2 * g + s2];
                    mma_bf16(d, qfh[ks], kh4[s2], kh4[2 + s2]);
                    mma_bf16(d, qfh[ks], kl4[s2], kl4[2 + s2]);
                    mma_bf16(d, qfl[ks], kh4[s2], kh4[2 + s2]);
                }
            }
        }

        float mx0 = sc[0][0], mx1 = sc[0][2];
        #pragma unroll
        for (int nt = 0; nt < 8; nt++) {
            mx0 = fmaxf(mx0, fmaxf(sc[nt][0], sc[nt][1]));
            mx1 = fmaxf(mx1, fmaxf(sc[nt][2], sc[nt][3]));
        }
        mx0 = fmaxf(mx0, __shfl_xor_sync(0xffffffffu, mx0, 1));
        mx0 = fmaxf(mx0, __shfl_xor_sync(0xffffffffu, mx0, 2));
        mx1 = fmaxf(mx1, __shfl_xor_sync(0xffffffffu, mx1, 1));
        mx1 = fmaxf(mx1, __shfl_xor_sync(0xffffffffu, mx1, 2));
        const float mn0 = fmaxf(m0, mx0), mn1 = fmaxf(m1, mx1);
        const float c0 = __expf(m0 - mn0), c1 = __expf(m1 - mn1);
        float s0 = 0.f, s1 = 0.f;
        #pragma unroll
        for (int nt = 0; nt < 8; nt++) {
            float p0 = __expf(sc[nt][0] - mn0); sc[nt][0] = p0; s0 += p0;
            float p1 = __expf(sc[nt][1] - mn0); sc[nt][1] = p1; s0 += p1;
            float p2 = __expf(sc[nt][2] - mn1); sc[nt][2] = p2; s1 += p2;
            float p3 = __expf(sc[nt][3] - mn1); sc[nt][3] = p3; s1 += p3;
        }
        s0 += __shfl_xor_sync(0xffffffffu, s0, 1);
        s0 += __shfl_xor_sync(0xffffffffu, s0, 2);
        s1 += __shfl_xor_sync(0xffffffffu, s1, 1);
        s1 += __shfl_xor_sync(0xffffffffu, s1, 2);
        l0 = l0 * c0 + s0; l1 = l1 * c1 + s1;
        m0 = mn0; m1 = mn1;
        #pragma unroll
        for (int dt = 0; dt < 8; dt++) {
            o[dt][0] *= c0; o[dt][1] *= c0;
            o[dt][2] *= c1; o[dt][3] *= c1;
        }

        const uint32_t vbh = sb + stg * 32768 + 16384, vbl = vbh + 8192;
        #pragma unroll
        for (int kk = 0; kk < 4; kk++) {
            uint32_t pah[4], pal[4];
            split_pack(sc[2 * kk][0],     sc[2 * kk][1],     pah[0], pal[0]);
            split_pack(sc[2 * kk][2],     sc[2 * kk][3],     pah[1], pal[1]);
            split_pack(sc[2 * kk + 1][0], sc[2 * kk + 1][1], pah[2], pal[2]);
            split_pack(sc[2 * kk + 1][2], sc[2 * kk + 1][3], pah[3], pal[3]);
            #pragma unroll
            for (int dg = 0; dg < 4; dg++) {
                const int key = kk * 16 + (lane & 15);
                const int c   = dg * 2 + (lane >> 4);
                const uint32_t off = (key * 8 + (c ^ (key & 7))) * 16;
                uint32_t vh4[4], vl4[4];
                ldm4t(vh4, vbh + off);
                ldm4t(vl4, vbl + off);
                mma_bf16(o[2 * dg], pah, vh4[0], vh4[1]);
                mma_bf16(o[2 * dg], pah, vl4[0], vl4[1]);
                mma_bf16(o[2 * dg], pal, vh4[0], vh4[1]);
                mma_bf16(o[2 * dg + 1], pah, vh4[2], vh4[3]);
                mma_bf16(o[2 * dg + 1], pah, vl4[2], vl4[3]);
                mma_bf16(o[2 * dg + 1], pal, vh4[2], vh4[3]);
            }
        }
        __syncthreads();
    }

    // ---- epilogue: write split bf16 attention output (token-major [8192,1024]) ----
    const float i0 = 1.f / l0, i1 = 1.f / l1;
    const int b = bh >> 4, h = bh & 15;
    const int r0 = qt0 + wid * 16 + (lane >> 2);
    const size_t base = (size_t)(b * NSEQ + r0) * DIMV + h * HD + (lane & 3) * 2;
    #pragma unroll
    for (int dt = 0; dt < 8; dt++) {
        uint32_t h0, l0v, h1, l1v;
        split_pack(o[dt][0] * i0, o[dt][1] * i0, h0, l0v);
        split_pack(o[dt][2] * i1, o[dt][3] * i1, h1, l1v);
        *reinterpret_cast<uint32_t*>(g_atth + base + dt * 8)            = h0;
        *reinterpret_cast<uint32_t*>(g_attl + base + dt * 8)            = l0v;
        *reinterpret_cast<uint32_t*>(g_atth + base + 8 * DIMV + dt * 8) = h1;
        *reinterpret_cast<uint32_t*>(g_attl + base + 8 * DIMV + dt * 8) = l1v;
    }
}

// ---------------------------------------------------------------------------
extern "C" void kernel_launch(void* const* d_in, const int* in_sizes, int n_in,
                              void* d_out, int out_size) {
    const float* x      = (const float*)d_in[0];
    const float* w_qkv  = (const float*)d_in[1];
    const float* w_proj = (const float*)d_in[2];
    const float* b_proj = (const float*)d_in[3];
    float* out = (float*)d_out;

    __nv_bfloat16 *wq_h, *wq_l, *wp_h, *wp_l, *xh, *xl, *ath, *atl;
    cudaGetSymbolAddress((void**)&wq_h, g_wqkv_h);
    cudaGetSymbolAddress((void**)&wq_l, g_wqkv_l);
    cudaGetSymbolAddress((void**)&wp_h, g_wproj_h);
    cudaGetSymbolAddress((void**)&wp_l, g_wproj_l);
    cudaGetSymbolAddress((void**)&xh, g_xh);
    cudaGetSymbolAddress((void**)&xl, g_xl);
    cudaGetSymbolAddress((void**)&ath, g_atth);
    cudaGetSymbolAddress((void**)&atl, g_attl);

    cudaFuncSetAttribute(attn_mma_kernel,
                         cudaFuncAttributeMaxDynamicSharedMemorySize, ATT_SMEM);
    cudaFuncSetAttribute(gemm_ps_kernel<1>,
                         cudaFuncAttributeMaxDynamicSharedMemorySize, GS_SMEM);
    cudaFuncSetAttribute(gemm_ps_kernel<2>,
                         cudaFuncAttributeMaxDynamicSharedMemorySize, GS_SMEM);

    transpose_split_kernel<<<dim3(DIMV / 32, N_QKV / 32), dim3(32, 8)>>>(
        w_qkv, wq_h, wq_l, DIMV, N_QKV);
    transpose_split_kernel<<<dim3(DIMV / 32, DIMV / 32), dim3(32, 8)>>>(
        w_proj, wp_h, wp_l, DIMV, DIMV);
    split_x_kernel<<<TOKENS, 256>>>(x);

    // qkv GEMM -> fused split + head-major scatter
    gemm_ps_kernel<2><<<dim3(N_QKV / 128, TOKENS / 128), 256, GS_SMEM>>>(
        xh, xl, wq_h, wq_l, nullptr, nullptr, TOKENS, N_QKV, DIMV);

    attn_mma_kernel<<<dim3(NBH, NSEQ / 128), 256, ATT_SMEM>>>();

    // proj GEMM + bias
    gemm_ps_kernel<1><<<dim3(DIMV / 128, TOKENS / 128), 256, GS_SMEM>>>(
        ath, atl, wp_h, wp_l, b_proj, out, TOKENS, DIMV, DIMV);
}